// round 11
// baseline (speedup 1.0000x reference)
#include <cuda_runtime.h>
#include <cuda_bf16.h>
#include <math.h>
#include <stdint.h>

#define DIMV   1024
#define HEADS  16
#define HD     64
#define BATCH  8
#define SEQ    1024
#define MTOT   (BATCH*SEQ)
#define SCALEF 0.125f

/* ------------------------------------------------------------------ */
#define PLANE (BATCH*HEADS*SEQ*HD)
__device__ __nv_bfloat16 g_xh[(size_t)MTOT*DIMV],  g_xl[(size_t)MTOT*DIMV];
__device__ __nv_bfloat16 g_wqh[3*DIMV*DIMV],       g_wql[3*DIMV*DIMV];
__device__ __nv_bfloat16 g_wph[DIMV*DIMV],         g_wpl[DIMV*DIMV];
__device__ __nv_bfloat16 g_qh[PLANE], g_ql[PLANE];
__device__ __nv_bfloat16 g_kh[PLANE], g_kl[PLANE];
__device__ __nv_bfloat16 g_vh[PLANE], g_vl[PLANE];
__device__ __nv_bfloat16 g_oh[(size_t)MTOT*DIMV],  g_ol[(size_t)MTOT*DIMV];

__device__ __forceinline__ uint32_t smem_u32(const void* p) {
    uint32_t a;
    asm("{ .reg .u64 t; cvta.to.shared.u64 t, %1; cvt.u32.u64 %0, t; }"
        : "=r"(a) : "l"(p));
    return a;
}
__device__ __forceinline__ void ldm_x4(uint32_t* r, uint32_t addr) {
    asm volatile("ldmatrix.sync.aligned.m8n8.x4.shared.b16 {%0,%1,%2,%3}, [%4];"
                 : "=r"(r[0]), "=r"(r[1]), "=r"(r[2]), "=r"(r[3]) : "r"(addr));
}
__device__ __forceinline__ void ldm_x4_t(uint32_t* r, uint32_t addr) {
    asm volatile("ldmatrix.sync.aligned.m8n8.x4.trans.shared.b16 {%0,%1,%2,%3}, [%4];"
                 : "=r"(r[0]), "=r"(r[1]), "=r"(r[2]), "=r"(r[3]) : "r"(addr));
}
__device__ __forceinline__ void mma_bf16(float* c, const uint32_t* a, const uint32_t* b) {
    asm volatile("mma.sync.aligned.m16n8k16.row.col.f32.bf16.bf16.f32 "
                 "{%0,%1,%2,%3}, {%4,%5,%6,%7}, {%8,%9}, {%0,%1,%2,%3};"
                 : "+f"(c[0]), "+f"(c[1]), "+f"(c[2]), "+f"(c[3])
                 : "r"(a[0]), "r"(a[1]), "r"(a[2]), "r"(a[3]), "r"(b[0]), "r"(b[1]));
}

/* ------------------------------------------------------------------ */
__global__ void __launch_bounds__(256) split_f32(
    const float* __restrict__ src, __nv_bfloat16* __restrict__ h,
    __nv_bfloat16* __restrict__ l, int n4)
{
    int i = blockIdx.x * blockDim.x + threadIdx.x;
    if (i >= n4) return;
    float4 v = *(const float4*)&src[(size_t)i * 4];
    __nv_bfloat162 h01 = __floats2bfloat162_rn(v.x, v.y);
    __nv_bfloat162 h23 = __floats2bfloat162_rn(v.z, v.w);
    __nv_bfloat162 l01 = __floats2bfloat162_rn(v.x - __bfloat162float(h01.x),
                                               v.y - __bfloat162float(h01.y));
    __nv_bfloat162 l23 = __floats2bfloat162_rn(v.z - __bfloat162float(h23.x),
                                               v.w - __bfloat162float(h23.y));
    *(uint2*)&h[(size_t)i * 4] = make_uint2(*(uint32_t*)&h01, *(uint32_t*)&h23);
    *(uint2*)&l[(size_t)i * 4] = make_uint2(*(uint32_t*)&l01, *(uint32_t*)&l23);
}

/* ------------------------------------------------------------------ */
/* GEMM v7: CTA 128x256, BK=16, 8 warps (2x4) each 64x64,              */
/* 1 CTA/SM (full reg budget), double-buffered smem, 1 sync/chunk.     */
/* 3-pass bf16 hi/lo. MODE 0: QKV scatter. MODE 1: +bias fp32 out.     */
/* ------------------------------------------------------------------ */
#define SP7     24                     /* bf16 elems per row (48 B) */
#define STG_E   (768*SP7)              /* elems per stage */
#define OFF_AH  0
#define OFF_AL  (128*SP7)
#define OFF_BH  (256*SP7)
#define OFF_BL  (512*SP7)
#define GSMEM7  (2*STG_E*2)            /* 73728 bytes */

template<int MODE>
__global__ void __launch_bounds__(256) gemm7(
    const __nv_bfloat16* __restrict__ Ah_, const __nv_bfloat16* __restrict__ Al_,
    const __nv_bfloat16* __restrict__ Bh, const __nv_bfloat16* __restrict__ Bl,
    int Nn, const float* __restrict__ bias, float* __restrict__ out)
{
    extern __shared__ __nv_bfloat16 sm7[];
    const uint32_t s0 = smem_u32(sm7);

    const __nv_bfloat16* Ah = (MODE == 1) ? g_oh : Ah_;
    const __nv_bfloat16* Al = (MODE == 1) ? g_ol : Al_;

    const int tid  = threadIdx.x;
    const int lane = tid & 31;
    const int wid  = tid >> 5;
    const int wm   = wid >> 2;
    const int wn   = wid & 3;
    const int m0   = blockIdx.y * 128;
    const int n0   = blockIdx.x * 256;

    const int a_lrow = (lane & 7) + ((lane >> 3) & 1) * 8;
    const int a_lkof = (lane >> 4) * 8;
    const int b_lrow = (lane & 7) + (lane >> 4) * 8;
    const int b_lkof = ((lane >> 3) & 1) * 8;

    float acc[4][8][4];
#pragma unroll
    for (int i = 0; i < 4; i++)
#pragma unroll
        for (int j = 0; j < 8; j++)
#pragma unroll
            for (int r = 0; r < 4; r++) acc[i][j][r] = 0.f;

    const int ar = tid >> 1;
    const int ac = (tid & 1) * 8;
    const uint32_t sA = (uint32_t)(ar * SP7 + ac) * 2;
    const uint32_t sB0 = (uint32_t)(tid * SP7) * 2;
    const size_t gA = (size_t)(m0 + ar) * DIMV + ac;
    const size_t gB = (size_t)(n0 + tid) * DIMV;

    uint4 r_ah, r_al, r_bh0, r_bh1, r_bl0, r_bl1;
    auto ldg_chunk = [&](int c) {
        const int k0 = c * 16;
        r_ah  = *(const uint4*)&Ah[gA + k0];
        r_al  = *(const uint4*)&Al[gA + k0];
        r_bh0 = *(const uint4*)&Bh[gB + k0];
        r_bh1 = *(const uint4*)&Bh[gB + k0 + 8];
        r_bl0 = *(const uint4*)&Bl[gB + k0];
        r_bl1 = *(const uint4*)&Bl[gB + k0 + 8];
    };
    auto sts_chunk = [&](int c) {
        const uint32_t sb = s0 + (uint32_t)((c & 1) * STG_E) * 2;
        asm volatile("st.shared.v4.b32 [%0], {%1,%2,%3,%4};" ::
            "r"(sb + OFF_AH*2 + sA), "r"(r_ah.x), "r"(r_ah.y), "r"(r_ah.z), "r"(r_ah.w));
        asm volatile("st.shared.v4.b32 [%0], {%1,%2,%3,%4};" ::
            "r"(sb + OFF_AL*2 + sA), "r"(r_al.x), "r"(r_al.y), "r"(r_al.z), "r"(r_al.w));
        asm volatile("st.shared.v4.b32 [%0], {%1,%2,%3,%4};" ::
            "r"(sb + OFF_BH*2 + sB0), "r"(r_bh0.x), "r"(r_bh0.y), "r"(r_bh0.z), "r"(r_bh0.w));
        asm volatile("st.shared.v4.b32 [%0], {%1,%2,%3,%4};" ::
            "r"(sb + OFF_BH*2 + sB0 + 16), "r"(r_bh1.x), "r"(r_bh1.y), "r"(r_bh1.z), "r"(r_bh1.w));
        asm volatile("st.shared.v4.b32 [%0], {%1,%2,%3,%4};" ::
            "r"(sb + OFF_BL*2 + sB0), "r"(r_bl0.x), "r"(r_bl0.y), "r"(r_bl0.z), "r"(r_bl0.w));
        asm volatile("st.shared.v4.b32 [%0], {%1,%2,%3,%4};" ::
            "r"(sb + OFF_BL*2 + sB0 + 16), "r"(r_bl1.x), "r"(r_bl1.y), "r"(r_bl1.z), "r"(r_bl1.w));
    };

    ldg_chunk(0);
    sts_chunk(0);
    __syncthreads();

    for (int c = 0; c < DIMV / 16; c++) {
        if (c + 1 < DIMV / 16) ldg_chunk(c + 1);

        const uint32_t st  = s0 + (uint32_t)((c & 1) * STG_E) * 2;
        const uint32_t uAh = st + OFF_AH * 2, uAl = st + OFF_AL * 2;
        const uint32_t uBh = st + OFF_BH * 2, uBl = st + OFF_BL * 2;

        uint32_t afh[4][4], afl[4][4];
#pragma unroll
        for (int mi = 0; mi < 4; mi++) {
            uint32_t aoff = (uint32_t)((wm * 64 + mi * 16 + a_lrow) * SP7 + a_lkof) * 2;
            ldm_x4(afh[mi], uAh + aoff);
            ldm_x4(afl[mi], uAl + aoff);
        }
        uint32_t bfh[4][4], bfl[4][4];
#pragma unroll
        for (int bi = 0; bi < 4; bi++) {
            uint32_t boff = (uint32_t)((wn * 64 + bi * 16 + b_lrow) * SP7 + b_lkof) * 2;
            ldm_x4(bfh[bi], uBh + boff);
            ldm_x4(bfl[bi], uBl + boff);
        }

#pragma unroll
        for (int mi = 0; mi < 4; mi++)
#pragma unroll
            for (int ni = 0; ni < 8; ni++)
                mma_bf16(acc[mi][ni], afh[mi], &bfh[ni >> 1][(ni & 1) * 2]);
#pragma unroll
        for (int mi = 0; mi < 4; mi++)
#pragma unroll
            for (int ni = 0; ni < 8; ni++)
                mma_bf16(acc[mi][ni], afh[mi], &bfl[ni >> 1][(ni & 1) * 2]);
#pragma unroll
        for (int mi = 0; mi < 4; mi++)
#pragma unroll
            for (int ni = 0; ni < 8; ni++)
                mma_bf16(acc[mi][ni], afl[mi], &bfh[ni >> 1][(ni & 1) * 2]);

        if (c + 1 < DIMV / 16) {
            sts_chunk(c + 1);
            __syncthreads();
        }
    }

    const int r_base = wm * 64 + (lane >> 2);
    const int c_base = wn * 64 + (lane & 3) * 2;
#pragma unroll
    for (int mi = 0; mi < 4; mi++) {
#pragma unroll
        for (int ni = 0; ni < 8; ni++) {
            int gcol = n0 + c_base + ni * 8;
#pragma unroll
            for (int half = 0; half < 2; half++) {
                int grow = m0 + r_base + mi * 16 + half * 8;
                float v0 = acc[mi][ni][half * 2 + 0];
                float v1 = acc[mi][ni][half * 2 + 1];
                if (MODE == 0) {
                    int qkv = gcol >> 10;
                    int hh  = (gcol >> 6) & 15;
                    int dd  = gcol & 63;
                    int b   = grow >> 10;
                    int sp  = grow & 1023;
                    size_t off = (((size_t)(b * HEADS + hh) * SEQ) + sp) * HD + dd;
                    if (qkv == 0) { v0 *= SCALEF; v1 *= SCALEF; }
                    __nv_bfloat16 h0 = __float2bfloat16_rn(v0);
                    __nv_bfloat16 h1 = __float2bfloat16_rn(v1);
                    __nv_bfloat16 l0 = __float2bfloat16_rn(v0 - __bfloat162float(h0));
                    __nv_bfloat16 l1 = __float2bfloat16_rn(v1 - __bfloat162float(h1));
                    __nv_bfloat16* ph = (qkv == 0) ? g_qh : (qkv == 1) ? g_kh : g_vh;
                    __nv_bfloat16* pl = (qkv == 0) ? g_ql : (qkv == 1) ? g_kl : g_vl;
                    *(__nv_bfloat162*)&ph[off] = __halves2bfloat162(h0, h1);
                    *(__nv_bfloat162*)&pl[off] = __halves2bfloat162(l0, l1);
                } else {
                    float2 bb = *(const float2*)&bias[gcol];
                    *(float2*)&out[(size_t)grow * Nn + gcol] =
                        make_float2(v0 + bb.x, v1 + bb.y);
                }
            }
        }
    }
}

/* ------------------------------------------------------------------ */
/* Tensor-core flash attention (round-10, passing)                     */
/* ------------------------------------------------------------------ */
#define QP 72

__global__ void __launch_bounds__(256) attn_mma()
{
    extern __shared__ __nv_bfloat16 smb[];
    __nv_bfloat16* Qh = smb;
    __nv_bfloat16* Ql = Qh + 128 * QP;
    __nv_bfloat16* Kh = Ql + 128 * QP;
    __nv_bfloat16* Kl = Kh + 64 * QP;
    __nv_bfloat16* Vh = Kl + 64 * QP;
    __nv_bfloat16* Vl = Vh + 64 * QP;

    const uint32_t uQh = smem_u32(Qh), uQl = smem_u32(Ql);
    const uint32_t uKh = smem_u32(Kh), uKl = smem_u32(Kl);
    const uint32_t uVh = smem_u32(Vh), uVl = smem_u32(Vl);

    const int tid  = threadIdx.x;
    const int lane = tid & 31;
    const int wid  = tid >> 5;
    const int bh   = blockIdx.y;
    const int m0   = blockIdx.x * 128;

    const size_t pbase = (size_t)bh * SEQ * HD;
    const __nv_bfloat16* pqh = g_qh + pbase;
    const __nv_bfloat16* pql = g_ql + pbase;
    const __nv_bfloat16* pkh = g_kh + pbase;
    const __nv_bfloat16* pkl = g_kl + pbase;
    const __nv_bfloat16* pvh = g_vh + pbase;
    const __nv_bfloat16* pvl = g_vl + pbase;

#pragma unroll
    for (int t = 0; t < 8; t++) {
        int idx = t * 256 + tid;
        int row = idx >> 4;
        int g   = idx & 15;
        size_t go = (size_t)(m0 + row) * HD + g * 4;
        *(uint2*)&Qh[row * QP + g * 4] = *(const uint2*)&pqh[go];
        *(uint2*)&Ql[row * QP + g * 4] = *(const uint2*)&pql[go];
    }

    float o[8][4];
#pragma unroll
    for (int n = 0; n < 8; n++)
#pragma unroll
        for (int r = 0; r < 4; r++) o[n][r] = 0.f;
    float mrow[2] = {-1e30f, -1e30f};
    float lrow[2] = {0.f, 0.f};

    const int a_row = wid * 16 + (lane & 15);
    const int a_kof = (lane >> 4) * 8;
    const int b_row = (lane & 7) + (lane >> 4) * 8;
    const int b_kof = ((lane >> 3) & 1) * 8;
    const int v_key = ((lane >> 3) & 1) * 8 + (lane & 7);
    const int v_col = (lane >> 4) * 8;

    for (int c = 0; c < 16; c++) {
        const int key0 = c * 64;
        __syncthreads();
#pragma unroll
        for (int t = 0; t < 4; t++) {
            int idx = t * 256 + tid;
            int row = idx >> 4;
            int g   = idx & 15;
            size_t go = (size_t)(key0 + row) * HD + g * 4;
            uint32_t so = row * QP + g * 4;
            *(uint2*)&Kh[so] = *(const uint2*)&pkh[go];
            *(uint2*)&Kl[so] = *(const uint2*)&pkl[go];
            *(uint2*)&Vh[so] = *(const uint2*)&pvh[go];
            *(uint2*)&Vl[so] = *(const uint2*)&pvl[go];
        }
        __syncthreads();

        float s[8][4];
#pragma unroll
        for (int n = 0; n < 8; n++)
#pragma unroll
            for (int r = 0; r < 4; r++) s[n][r] = 0.f;

#pragma unroll
        for (int kk = 0; kk < 4; kk++) {
            uint32_t qhf[4], qlf[4];
            uint32_t aoff = (uint32_t)(a_row * QP + kk * 16 + a_kof) * 2;
            ldm_x4(qhf, uQh + aoff);
            ldm_x4(qlf, uQl + aoff);

            uint32_t kbh[4][4], kbl[4][4];
#pragma unroll
            for (int bi = 0; bi < 4; bi++) {
                uint32_t boff = (uint32_t)((bi * 16 + b_row) * QP + kk * 16 + b_kof) * 2;
                ldm_x4(kbh[bi], uKh + boff);
                ldm_x4(kbl[bi], uKl + boff);
            }
#pragma unroll
            for (int ni = 0; ni < 8; ni++)
                mma_bf16(s[ni], qhf, &kbh[ni >> 1][(ni & 1) * 2]);
#pragma unroll
            for (int ni = 0; ni < 8; ni++)
                mma_bf16(s[ni], qhf, &kbl[ni >> 1][(ni & 1) * 2]);
#pragma unroll
            for (int ni = 0; ni < 8; ni++)
                mma_bf16(s[ni], qlf, &kbh[ni >> 1][(ni & 1) * 2]);
        }

        float alpha[2];
#pragma unroll
        for (int r = 0; r < 2; r++) {
            float mx = -1e30f;
#pragma unroll
            for (int ni = 0; ni < 8; ni++)
                mx = fmaxf(mx, fmaxf(s[ni][r * 2], s[ni][r * 2 + 1]));
            mx = fmaxf(mx, __shfl_xor_sync(0xffffffffu, mx, 1));
            mx = fmaxf(mx, __shfl_xor_sync(0xffffffffu, mx, 2));
            float mnew = fmaxf(mrow[r], mx);
            alpha[r] = __expf(mrow[r] - mnew);
            mrow[r] = mnew;
            float ls = 0.f;
#pragma unroll
            for (int ni = 0; ni < 8; ni++) {
                s[ni][r * 2]     = __expf(s[ni][r * 2]     - mnew);
                s[ni][r * 2 + 1] = __expf(s[ni][r * 2 + 1] - mnew);
                ls += s[ni][r * 2] + s[ni][r * 2 + 1];
            }
            ls += __shfl_xor_sync(0xffffffffu, ls, 1);
            ls += __shfl_xor_sync(0xffffffffu, ls, 2);
            lrow[r] = lrow[r] * alpha[r] + ls;
#pragma unroll
            for (int ni = 0; ni < 8; ni++) {
                o[ni][r * 2]     *= alpha[r];
                o[ni][r * 2 + 1] *= alpha[r];
            }
        }

#pragma unroll
        for (int kk = 0; kk < 4; kk++) {
            uint32_t pha[4], pla[4];
#pragma unroll
            for (int q = 0; q < 4; q++) {
                float f0 = (q & 2) ? s[2 * kk + 1][(q & 1) * 2]     : s[2 * kk][(q & 1) * 2];
                float f1 = (q & 2) ? s[2 * kk + 1][(q & 1) * 2 + 1] : s[2 * kk][(q & 1) * 2 + 1];
                __nv_bfloat162 h2 = __floats2bfloat162_rn(f0, f1);
                __nv_bfloat162 l2 = __floats2bfloat162_rn(f0 - __bfloat162float(h2.x),
                                                          f1 - __bfloat162float(h2.y));
                pha[q] = *(uint32_t*)&h2;
                pla[q] = *(uint32_t*)&l2;
            }
            uint32_t vbh[4][4], vbl[4][4];
#pragma unroll
            for (int np = 0; np < 4; np++) {
                uint32_t voff = (uint32_t)((kk * 16 + v_key) * QP + np * 16 + v_col) * 2;
                ldm_x4_t(vbh[np], uVh + voff);
                ldm_x4_t(vbl[np], uVl + voff);
            }
#pragma unroll
            for (int ni = 0; ni < 8; ni++)
                mma_bf16(o[ni], pha, &vbh[ni >> 1][(ni & 1) * 2]);
#pragma unroll
            for (int ni = 0; ni < 8; ni++)
                mma_bf16(o[ni], pha, &vbl[ni >> 1][(ni & 1) * 2]);
#pragma unroll
            for (int ni = 0; ni < 8; ni++)
                mma_bf16(o[ni], pla, &vbh[ni >> 1][(ni & 1) * 2]);
        }
    }

    const int b = bh >> 4;
    const int h = bh & 15;
#pragma unroll
    for (int r = 0; r < 2; r++) {
        float inv = 1.f / lrow[r];
        int row = m0 + wid * 16 + (lane >> 2) + r * 8;
        size_t base = ((size_t)(b * SEQ + row)) * DIMV + h * HD + (lane & 3) * 2;
#pragma unroll
        for (int ni = 0; ni < 8; ni++) {
            float f0 = o[ni][r * 2] * inv;
            float f1 = o[ni][r * 2 + 1] * inv;
            __nv_bfloat162 h2 = __floats2bfloat162_rn(f0, f1);
            __nv_bfloat162 l2 = __floats2bfloat162_rn(f0 - __bfloat162float(h2.x),
                                                      f1 - __bfloat162float(h2.y));
            *(__nv_bfloat162*)&g_oh[base + ni * 8] = h2;
            *(__nv_bfloat162*)&g_ol[base + ni * 8] = l2;
        }
    }
}

/* ------------------------------------------------------------------ */
extern "C" void kernel_launch(void* const* d_in, const int* in_sizes, int n_in,
                              void* d_out, int out_size)
{
    const float* x = nullptr;
    const float* Wqkv = nullptr;
    const float* Wproj = nullptr;
    const float* bproj = nullptr;
    for (int i = 0; i < n_in; i++) {
        switch (in_sizes[i]) {
            case 8388608: x     = (const float*)d_in[i]; break;
            case 3145728: Wqkv  = (const float*)d_in[i]; break;
            case 1048576: Wproj = (const float*)d_in[i]; break;
            case 1024:    bproj = (const float*)d_in[i]; break;
            default: break;
        }
    }
    float* out = (float*)d_out;

    __nv_bfloat16 *xh, *xl, *wqh, *wql, *wph, *wpl;
    cudaGetSymbolAddress((void**)&xh,  g_xh);
    cudaGetSymbolAddress((void**)&xl,  g_xl);
    cudaGetSymbolAddress((void**)&wqh, g_wqh);
    cudaGetSymbolAddress((void**)&wql, g_wql);
    cudaGetSymbolAddress((void**)&wph, g_wph);
    cudaGetSymbolAddress((void**)&wpl, g_wpl);

    split_f32<<<(8388608/4 + 255)/256, 256>>>(x,     xh,  xl,  8388608/4);
    split_f32<<<(3145728/4 + 255)/256, 256>>>(Wqkv,  wqh, wql, 3145728/4);
    split_f32<<<(1048576/4 + 255)/256, 256>>>(Wproj, wph, wpl, 1048576/4);

    {
        cudaFuncSetAttribute(gemm7<0>, cudaFuncAttributeMaxDynamicSharedMemorySize,
                             GSMEM7);
        dim3 grid(3 * DIMV / 256, MTOT / 128);
        gemm7<0><<<grid, 256, GSMEM7>>>(xh, xl, wqh, wql, 3 * DIMV, nullptr, nullptr);
    }
    {
        size_t smem = (size_t)(2 * 128 + 4 * 64) * QP * sizeof(__nv_bfloat16);
        cudaFuncSetAttribute(attn_mma, cudaFuncAttributeMaxDynamicSharedMemorySize,
                             (int)smem);
        dim3 grid(SEQ / 128, BATCH * HEADS);
        attn_mma<<<grid, 256, smem>>>();
    }
    {
        cudaFuncSetAttribute(gemm7<1>, cudaFuncAttributeMaxDynamicSharedMemorySize,
                             GSMEM7);
        dim3 grid(DIMV / 256, MTOT / 128);
        gemm7<1><<<grid, 256, GSMEM7>>>(nullptr, nullptr, wph, wpl, DIMV, bproj, out);
    }
    (void)out_size; (void)n_in;
}

// round 12
// speedup vs baseline: 1.7688x; 1.7688x over previous
#include <cuda_runtime.h>
#include <cuda_bf16.h>
#include <math.h>
#include <stdint.h>

#define DIMV   1024
#define HEADS  16
#define HD     64
#define BATCH  8
#define SEQ    1024
#define MTOT   (BATCH*SEQ)
#define SCALEF 0.125f

/* ------------------------------------------------------------------ */
/* scratch planes                                                      */
/* ------------------------------------------------------------------ */
#define PLANE (BATCH*HEADS*SEQ*HD)
__device__ __nv_bfloat16 g_qh[PLANE], g_ql[PLANE];
__device__ __nv_bfloat16 g_kh[PLANE], g_kl[PLANE];
__device__ __nv_bfloat16 g_vh[PLANE], g_vl[PLANE];
__device__ __nv_bfloat16 g_oh[(size_t)MTOT*DIMV], g_ol[(size_t)MTOT*DIMV];

__device__ __forceinline__ uint32_t smem_u32(const void* p) {
    uint32_t a;
    asm("{ .reg .u64 t; cvta.to.shared.u64 t, %1; cvt.u32.u64 %0, t; }"
        : "=r"(a) : "l"(p));
    return a;
}
__device__ __forceinline__ void ldm_x4(uint32_t* r, uint32_t addr) {
    asm volatile("ldmatrix.sync.aligned.m8n8.x4.shared.b16 {%0,%1,%2,%3}, [%4];"
                 : "=r"(r[0]), "=r"(r[1]), "=r"(r[2]), "=r"(r[3]) : "r"(addr));
}
__device__ __forceinline__ void ldm_x4_t(uint32_t* r, uint32_t addr) {
    asm volatile("ldmatrix.sync.aligned.m8n8.x4.trans.shared.b16 {%0,%1,%2,%3}, [%4];"
                 : "=r"(r[0]), "=r"(r[1]), "=r"(r[2]), "=r"(r[3]) : "r"(addr));
}
__device__ __forceinline__ void mma_bf16(float* c, const uint32_t* a, const uint32_t* b) {
    asm volatile("mma.sync.aligned.m16n8k16.row.col.f32.bf16.bf16.f32 "
                 "{%0,%1,%2,%3}, {%4,%5,%6,%7}, {%8,%9}, {%0,%1,%2,%3};"
                 : "+f"(c[0]), "+f"(c[1]), "+f"(c[2]), "+f"(c[3])
                 : "r"(a[0]), "r"(a[1]), "r"(a[2]), "r"(a[3]), "r"(b[0]), "r"(b[1]));
}

#define SP 40

/* ------------------------------------------------------------------ */
/* QKV GEMM: round-4 proven. fp32 x and W_qkv, inline bf16 hi/lo       */
/* split, 128x128 tile, BK=32, 8 warps 2x4, 2 CTA/SM.                  */
/* Epilogue scatters q/k/v bf16 hi/lo planes (Q pre-scaled).           */
/* ------------------------------------------------------------------ */
__global__ void __launch_bounds__(256, 2) gemm_qkv(
    const float* __restrict__ Ap, const float* __restrict__ Bw)
{
    __shared__ __nv_bfloat16 sAh[128 * SP];
    __shared__ __nv_bfloat16 sAl[128 * SP];
    __shared__ __nv_bfloat16 sBh[128 * SP];
    __shared__ __nv_bfloat16 sBl[128 * SP];

    const int tid  = threadIdx.x;
    const int lane = tid & 31;
    const int wid  = tid >> 5;
    const int wm   = wid >> 2;
    const int wn   = wid & 3;
    const int m0   = blockIdx.y * 128;
    const int n0   = blockIdx.x * 128;

    const uint32_t uAh = smem_u32(sAh);
    const uint32_t uAl = smem_u32(sAl);
    const uint32_t uBh = smem_u32(sBh);
    const uint32_t uBl = smem_u32(sBl);

    const int a_lrow = (lane & 7) + ((lane >> 3) & 1) * 8;
    const int a_lkof = (lane >> 4) * 8;
    const int b_lrow = (lane & 7) + (lane >> 4) * 8;
    const int b_lkof = ((lane >> 3) & 1) * 8;

    float acc[4][4][4];
#pragma unroll
    for (int i = 0; i < 4; i++)
#pragma unroll
        for (int j = 0; j < 4; j++)
#pragma unroll
            for (int r = 0; r < 4; r++) acc[i][j][r] = 0.f;

    const int row_l = tid >> 3;
    const int cq    = tid & 7;

    for (int k0 = 0; k0 < DIMV; k0 += 32) {
#pragma unroll
        for (int t = 0; t < 4; t++) {
            int row = row_l + t * 32;
            uint32_t so = (uint32_t)(row * SP + cq * 4) * 2;

            float4 a = *(const float4*)&Ap[(size_t)(m0 + row) * DIMV + k0 + cq * 4];
            __nv_bfloat162 h01 = __floats2bfloat162_rn(a.x, a.y);
            __nv_bfloat162 h23 = __floats2bfloat162_rn(a.z, a.w);
            __nv_bfloat162 l01 = __floats2bfloat162_rn(a.x - __bfloat162float(h01.x),
                                                       a.y - __bfloat162float(h01.y));
            __nv_bfloat162 l23 = __floats2bfloat162_rn(a.z - __bfloat162float(h23.x),
                                                       a.w - __bfloat162float(h23.y));
            asm volatile("st.shared.v2.u32 [%0], {%1,%2};" ::
                "r"(uAh + so), "r"(*(uint32_t*)&h01), "r"(*(uint32_t*)&h23));
            asm volatile("st.shared.v2.u32 [%0], {%1,%2};" ::
                "r"(uAl + so), "r"(*(uint32_t*)&l01), "r"(*(uint32_t*)&l23));

            float4 b = *(const float4*)&Bw[(size_t)(n0 + row) * DIMV + k0 + cq * 4];
            __nv_bfloat162 bh01 = __floats2bfloat162_rn(b.x, b.y);
            __nv_bfloat162 bh23 = __floats2bfloat162_rn(b.z, b.w);
            __nv_bfloat162 bl01 = __floats2bfloat162_rn(b.x - __bfloat162float(bh01.x),
                                                        b.y - __bfloat162float(bh01.y));
            __nv_bfloat162 bl23 = __floats2bfloat162_rn(b.z - __bfloat162float(bh23.x),
                                                        b.w - __bfloat162float(bh23.y));
            asm volatile("st.shared.v2.u32 [%0], {%1,%2};" ::
                "r"(uBh + so), "r"(*(uint32_t*)&bh01), "r"(*(uint32_t*)&bh23));
            asm volatile("st.shared.v2.u32 [%0], {%1,%2};" ::
                "r"(uBl + so), "r"(*(uint32_t*)&bl01), "r"(*(uint32_t*)&bl23));
        }
        __syncthreads();

#pragma unroll
        for (int ks = 0; ks < 2; ks++) {
            const int kk = ks * 16;
            uint32_t bfh[2][4], bfl[2][4];
#pragma unroll
            for (int bi = 0; bi < 2; bi++) {
                uint32_t boff = (uint32_t)((wn * 32 + bi * 16 + b_lrow) * SP
                                           + kk + b_lkof) * 2;
                ldm_x4(bfh[bi], uBh + boff);
                ldm_x4(bfl[bi], uBl + boff);
            }
#pragma unroll
            for (int mi = 0; mi < 4; mi++) {
                uint32_t af_h[4], af_l[4];
                uint32_t aoff = (uint32_t)((wm * 64 + mi * 16 + a_lrow) * SP
                                           + kk + a_lkof) * 2;
                ldm_x4(af_h, uAh + aoff);
                ldm_x4(af_l, uAl + aoff);
#pragma unroll
                for (int ni = 0; ni < 4; ni++) {
                    const uint32_t* bh = &bfh[ni >> 1][(ni & 1) * 2];
                    const uint32_t* bl = &bfl[ni >> 1][(ni & 1) * 2];
                    mma_bf16(acc[mi][ni], af_h, bh);
                    mma_bf16(acc[mi][ni], af_h, bl);
                    mma_bf16(acc[mi][ni], af_l, bh);
                }
            }
        }
        __syncthreads();
    }

    const int r_base = wm * 64 + (lane >> 2);
    const int c_base = wn * 32 + (lane & 3) * 2;
#pragma unroll
    for (int mi = 0; mi < 4; mi++) {
#pragma unroll
        for (int ni = 0; ni < 4; ni++) {
            int gcol = n0 + c_base + ni * 8;
#pragma unroll
            for (int half = 0; half < 2; half++) {
                int grow = m0 + r_base + mi * 16 + half * 8;
                float v0 = acc[mi][ni][half * 2 + 0];
                float v1 = acc[mi][ni][half * 2 + 1];
                int qkv = gcol >> 10;
                int hh  = (gcol >> 6) & 15;
                int dd  = gcol & 63;
                int b   = grow >> 10;
                int sp  = grow & 1023;
                size_t off = (((size_t)(b * HEADS + hh) * SEQ) + sp) * HD + dd;
                if (qkv == 0) { v0 *= SCALEF; v1 *= SCALEF; }
                __nv_bfloat16 h0 = __float2bfloat16_rn(v0);
                __nv_bfloat16 h1 = __float2bfloat16_rn(v1);
                __nv_bfloat16 l0 = __float2bfloat16_rn(v0 - __bfloat162float(h0));
                __nv_bfloat16 l1 = __float2bfloat16_rn(v1 - __bfloat162float(h1));
                __nv_bfloat16* ph = (qkv == 0) ? g_qh : (qkv == 1) ? g_kh : g_vh;
                __nv_bfloat16* pl = (qkv == 0) ? g_ql : (qkv == 1) ? g_kl : g_vl;
                *(__nv_bfloat162*)&ph[off] = __halves2bfloat162(h0, h1);
                *(__nv_bfloat162*)&pl[off] = __halves2bfloat162(l0, l1);
            }
        }
    }
}

/* ------------------------------------------------------------------ */
/* Proj GEMM (hybrid): A from bf16 o-planes (direct LDG, no convert),  */
/* W_proj fp32 inline-converted. Same tile/compute as QKV. +bias out.  */
/* ------------------------------------------------------------------ */
__global__ void __launch_bounds__(256, 2) gemm_proj(
    const float* __restrict__ Bw, const float* __restrict__ bias,
    float* __restrict__ out)
{
    __shared__ __nv_bfloat16 sAh[128 * SP];
    __shared__ __nv_bfloat16 sAl[128 * SP];
    __shared__ __nv_bfloat16 sBh[128 * SP];
    __shared__ __nv_bfloat16 sBl[128 * SP];

    const int tid  = threadIdx.x;
    const int lane = tid & 31;
    const int wid  = tid >> 5;
    const int wm   = wid >> 2;
    const int wn   = wid & 3;
    const int m0   = blockIdx.y * 128;
    const int n0   = blockIdx.x * 128;

    const uint32_t uAh = smem_u32(sAh);
    const uint32_t uAl = smem_u32(sAl);
    const uint32_t uBh = smem_u32(sBh);
    const uint32_t uBl = smem_u32(sBl);

    const int a_lrow = (lane & 7) + ((lane >> 3) & 1) * 8;
    const int a_lkof = (lane >> 4) * 8;
    const int b_lrow = (lane & 7) + (lane >> 4) * 8;
    const int b_lkof = ((lane >> 3) & 1) * 8;

    float acc[4][4][4];
#pragma unroll
    for (int i = 0; i < 4; i++)
#pragma unroll
        for (int j = 0; j < 4; j++)
#pragma unroll
            for (int r = 0; r < 4; r++) acc[i][j][r] = 0.f;

    /* A loader: bf16 planes. thread -> row tid>>1, 32B half (tid&1) */
    const int a_r  = tid >> 1;
    const int a_c  = (tid & 1) * 16;                 /* bf16 elem 0 / 16 */
    const uint32_t a_so = (uint32_t)(a_r * SP + a_c) * 2;
    const size_t a_go = (size_t)(m0 + a_r) * DIMV + a_c;

    /* B loader: fp32 W, round-4 indexing */
    const int row_l = tid >> 3;
    const int cq    = tid & 7;

    for (int k0 = 0; k0 < DIMV; k0 += 32) {
        /* A: direct bf16 copies (2 x 16B per plane) */
        uint4 ah0 = *(const uint4*)&g_oh[a_go + k0];
        uint4 ah1 = *(const uint4*)&g_oh[a_go + k0 + 8];
        uint4 al0 = *(const uint4*)&g_ol[a_go + k0];
        uint4 al1 = *(const uint4*)&g_ol[a_go + k0 + 8];

        /* previous compute must finish before overwriting smem */
        __syncthreads();

        asm volatile("st.shared.v4.b32 [%0], {%1,%2,%3,%4};" ::
            "r"(uAh + a_so), "r"(ah0.x), "r"(ah0.y), "r"(ah0.z), "r"(ah0.w));
        asm volatile("st.shared.v4.b32 [%0], {%1,%2,%3,%4};" ::
            "r"(uAh + a_so + 16), "r"(ah1.x), "r"(ah1.y), "r"(ah1.z), "r"(ah1.w));
        asm volatile("st.shared.v4.b32 [%0], {%1,%2,%3,%4};" ::
            "r"(uAl + a_so), "r"(al0.x), "r"(al0.y), "r"(al0.z), "r"(al0.w));
        asm volatile("st.shared.v4.b32 [%0], {%1,%2,%3,%4};" ::
            "r"(uAl + a_so + 16), "r"(al1.x), "r"(al1.y), "r"(al1.z), "r"(al1.w));

        /* B: fp32 load + split (round-4 path) */
#pragma unroll
        for (int t = 0; t < 4; t++) {
            int row = row_l + t * 32;
            uint32_t so = (uint32_t)(row * SP + cq * 4) * 2;
            float4 b = *(const float4*)&Bw[(size_t)(n0 + row) * DIMV + k0 + cq * 4];
            __nv_bfloat162 bh01 = __floats2bfloat162_rn(b.x, b.y);
            __nv_bfloat162 bh23 = __floats2bfloat162_rn(b.z, b.w);
            __nv_bfloat162 bl01 = __floats2bfloat162_rn(b.x - __bfloat162float(bh01.x),
                                                        b.y - __bfloat162float(bh01.y));
            __nv_bfloat162 bl23 = __floats2bfloat162_rn(b.z - __bfloat162float(bh23.x),
                                                        b.w - __bfloat162float(bh23.y));
            asm volatile("st.shared.v2.u32 [%0], {%1,%2};" ::
                "r"(uBh + so), "r"(*(uint32_t*)&bh01), "r"(*(uint32_t*)&bh23));
            asm volatile("st.shared.v2.u32 [%0], {%1,%2};" ::
                "r"(uBl + so), "r"(*(uint32_t*)&bl01), "r"(*(uint32_t*)&bl23));
        }
        __syncthreads();

#pragma unroll
        for (int ks = 0; ks < 2; ks++) {
            const int kk = ks * 16;
            uint32_t bfh[2][4], bfl[2][4];
#pragma unroll
            for (int bi = 0; bi < 2; bi++) {
                uint32_t boff = (uint32_t)((wn * 32 + bi * 16 + b_lrow) * SP
                                           + kk + b_lkof) * 2;
                ldm_x4(bfh[bi], uBh + boff);
                ldm_x4(bfl[bi], uBl + boff);
            }
#pragma unroll
            for (int mi = 0; mi < 4; mi++) {
                uint32_t af_h[4], af_l[4];
                uint32_t aoff = (uint32_t)((wm * 64 + mi * 16 + a_lrow) * SP
                                           + kk + a_lkof) * 2;
                ldm_x4(af_h, uAh + aoff);
                ldm_x4(af_l, uAl + aoff);
#pragma unroll
                for (int ni = 0; ni < 4; ni++) {
                    const uint32_t* bh = &bfh[ni >> 1][(ni & 1) * 2];
                    const uint32_t* bl = &bfl[ni >> 1][(ni & 1) * 2];
                    mma_bf16(acc[mi][ni], af_h, bh);
                    mma_bf16(acc[mi][ni], af_h, bl);
                    mma_bf16(acc[mi][ni], af_l, bh);
                }
            }
        }
    }

    const int r_base = wm * 64 + (lane >> 2);
    const int c_base = wn * 32 + (lane & 3) * 2;
#pragma unroll
    for (int mi = 0; mi < 4; mi++) {
#pragma unroll
        for (int ni = 0; ni < 4; ni++) {
            int gcol = n0 + c_base + ni * 8;
#pragma unroll
            for (int half = 0; half < 2; half++) {
                int grow = m0 + r_base + mi * 16 + half * 8;
                float2 bb = *(const float2*)&bias[gcol];
                *(float2*)&out[(size_t)grow * DIMV + gcol] =
                    make_float2(acc[mi][ni][half * 2 + 0] + bb.x,
                                acc[mi][ni][half * 2 + 1] + bb.y);
            }
        }
    }
}

/* ------------------------------------------------------------------ */
/* Tensor-core flash attention (proven), epilogue -> o planes          */
/* ------------------------------------------------------------------ */
#define QP 72

__global__ void __launch_bounds__(256) attn_mma()
{
    extern __shared__ __nv_bfloat16 smb[];
    __nv_bfloat16* Qh = smb;
    __nv_bfloat16* Ql = Qh + 128 * QP;
    __nv_bfloat16* Kh = Ql + 128 * QP;
    __nv_bfloat16* Kl = Kh + 64 * QP;
    __nv_bfloat16* Vh = Kl + 64 * QP;
    __nv_bfloat16* Vl = Vh + 64 * QP;

    const uint32_t uQh = smem_u32(Qh), uQl = smem_u32(Ql);
    const uint32_t uKh = smem_u32(Kh), uKl = smem_u32(Kl);
    const uint32_t uVh = smem_u32(Vh), uVl = smem_u32(Vl);

    const int tid  = threadIdx.x;
    const int lane = tid & 31;
    const int wid  = tid >> 5;
    const int bh   = blockIdx.y;
    const int m0   = blockIdx.x * 128;

    const size_t pbase = (size_t)bh * SEQ * HD;
    const __nv_bfloat16* pqh = g_qh + pbase;
    const __nv_bfloat16* pql = g_ql + pbase;
    const __nv_bfloat16* pkh = g_kh + pbase;
    const __nv_bfloat16* pkl = g_kl + pbase;
    const __nv_bfloat16* pvh = g_vh + pbase;
    const __nv_bfloat16* pvl = g_vl + pbase;

#pragma unroll
    for (int t = 0; t < 8; t++) {
        int idx = t * 256 + tid;
        int row = idx >> 4;
        int g   = idx & 15;
        size_t go = (size_t)(m0 + row) * HD + g * 4;
        *(uint2*)&Qh[row * QP + g * 4] = *(const uint2*)&pqh[go];
        *(uint2*)&Ql[row * QP + g * 4] = *(const uint2*)&pql[go];
    }

    float o[8][4];
#pragma unroll
    for (int n = 0; n < 8; n++)
#pragma unroll
        for (int r = 0; r < 4; r++) o[n][r] = 0.f;
    float mrow[2] = {-1e30f, -1e30f};
    float lrow[2] = {0.f, 0.f};

    const int a_row = wid * 16 + (lane & 15);
    const int a_kof = (lane >> 4) * 8;
    const int b_row = (lane & 7) + (lane >> 4) * 8;
    const int b_kof = ((lane >> 3) & 1) * 8;
    const int v_key = ((lane >> 3) & 1) * 8 + (lane & 7);
    const int v_col = (lane >> 4) * 8;

    for (int c = 0; c < 16; c++) {
        const int key0 = c * 64;
        __syncthreads();
#pragma unroll
        for (int t = 0; t < 4; t++) {
            int idx = t * 256 + tid;
            int row = idx >> 4;
            int g   = idx & 15;
            size_t go = (size_t)(key0 + row) * HD + g * 4;
            uint32_t so = row * QP + g * 4;
            *(uint2*)&Kh[so] = *(const uint2*)&pkh[go];
            *(uint2*)&Kl[so] = *(const uint2*)&pkl[go];
            *(uint2*)&Vh[so] = *(const uint2*)&pvh[go];
            *(uint2*)&Vl[so] = *(const uint2*)&pvl[go];
        }
        __syncthreads();

        float s[8][4];
#pragma unroll
        for (int n = 0; n < 8; n++)
#pragma unroll
            for (int r = 0; r < 4; r++) s[n][r] = 0.f;

#pragma unroll
        for (int kk = 0; kk < 4; kk++) {
            uint32_t qhf[4], qlf[4];
            uint32_t aoff = (uint32_t)(a_row * QP + kk * 16 + a_kof) * 2;
            ldm_x4(qhf, uQh + aoff);
            ldm_x4(qlf, uQl + aoff);

            uint32_t kbh[4][4], kbl[4][4];
#pragma unroll
            for (int bi = 0; bi < 4; bi++) {
                uint32_t boff = (uint32_t)((bi * 16 + b_row) * QP + kk * 16 + b_kof) * 2;
                ldm_x4(kbh[bi], uKh + boff);
                ldm_x4(kbl[bi], uKl + boff);
            }
#pragma unroll
            for (int ni = 0; ni < 8; ni++)
                mma_bf16(s[ni], qhf, &kbh[ni >> 1][(ni & 1) * 2]);
#pragma unroll
            for (int ni = 0; ni < 8; ni++)
                mma_bf16(s[ni], qhf, &kbl[ni >> 1][(ni & 1) * 2]);
#pragma unroll
            for (int ni = 0; ni < 8; ni++)
                mma_bf16(s[ni], qlf, &kbh[ni >> 1][(ni & 1) * 2]);
        }

        float alpha[2];
#pragma unroll
        for (int r = 0; r < 2; r++) {
            float mx = -1e30f;
#pragma unroll
            for (int ni = 0; ni < 8; ni++)
                mx = fmaxf(mx, fmaxf(s[ni][r * 2], s[ni][r * 2 + 1]));
            mx = fmaxf(mx, __shfl_xor_sync(0xffffffffu, mx, 1));
            mx = fmaxf(mx, __shfl_xor_sync(0xffffffffu, mx, 2));
            float mnew = fmaxf(mrow[r], mx);
            alpha[r] = __expf(mrow[r] - mnew);
            mrow[r] = mnew;
            float ls = 0.f;
#pragma unroll
            for (int ni = 0; ni < 8; ni++) {
                s[ni][r * 2]     = __expf(s[ni][r * 2]     - mnew);
                s[ni][r * 2 + 1] = __expf(s[ni][r * 2 + 1] - mnew);
                ls += s[ni][r * 2] + s[ni][r * 2 + 1];
            }
            ls += __shfl_xor_sync(0xffffffffu, ls, 1);
            ls += __shfl_xor_sync(0xffffffffu, ls, 2);
            lrow[r] = lrow[r] * alpha[r] + ls;
#pragma unroll
            for (int ni = 0; ni < 8; ni++) {
                o[ni][r * 2]     *= alpha[r];
                o[ni][r * 2 + 1] *= alpha[r];
            }
        }

#pragma unroll
        for (int kk = 0; kk < 4; kk++) {
            uint32_t pha[4], pla[4];
#pragma unroll
            for (int q = 0; q < 4; q++) {
                float f0 = (q & 2) ? s[2 * kk + 1][(q & 1) * 2]     : s[2 * kk][(q & 1) * 2];
                float f1 = (q & 2) ? s[2 * kk + 1][(q & 1) * 2 + 1] : s[2 * kk][(q & 1) * 2 + 1];
                __nv_bfloat162 h2 = __floats2bfloat162_rn(f0, f1);
                __nv_bfloat162 l2 = __floats2bfloat162_rn(f0 - __bfloat162float(h2.x),
                                                          f1 - __bfloat162float(h2.y));
                pha[q] = *(uint32_t*)&h2;
                pla[q] = *(uint32_t*)&l2;
            }
            uint32_t vbh[4][4], vbl[4][4];
#pragma unroll
            for (int np = 0; np < 4; np++) {
                uint32_t voff = (uint32_t)((kk * 16 + v_key) * QP + np * 16 + v_col) * 2;
                ldm_x4_t(vbh[np], uVh + voff);
                ldm_x4_t(vbl[np], uVl + voff);
            }
#pragma unroll
            for (int ni = 0; ni < 8; ni++)
                mma_bf16(o[ni], pha, &vbh[ni >> 1][(ni & 1) * 2]);
#pragma unroll
            for (int ni = 0; ni < 8; ni++)
                mma_bf16(o[ni], pha, &vbl[ni >> 1][(ni & 1) * 2]);
#pragma unroll
            for (int ni = 0; ni < 8; ni++)
                mma_bf16(o[ni], pla, &vbh[ni >> 1][(ni & 1) * 2]);
        }
    }

    const int b = bh >> 4;
    const int h = bh & 15;
#pragma unroll
    for (int r = 0; r < 2; r++) {
        float inv = 1.f / lrow[r];
        int row = m0 + wid * 16 + (lane >> 2) + r * 8;
        size_t base = ((size_t)(b * SEQ + row)) * DIMV + h * HD + (lane & 3) * 2;
#pragma unroll
        for (int ni = 0; ni < 8; ni++) {
            float f0 = o[ni][r * 2] * inv;
            float f1 = o[ni][r * 2 + 1] * inv;
            __nv_bfloat162 h2 = __floats2bfloat162_rn(f0, f1);
            __nv_bfloat162 l2 = __floats2bfloat162_rn(f0 - __bfloat162float(h2.x),
                                                      f1 - __bfloat162float(h2.y));
            *(__nv_bfloat162*)&g_oh[base + ni * 8] = h2;
            *(__nv_bfloat162*)&g_ol[base + ni * 8] = l2;
        }
    }
}

/* ------------------------------------------------------------------ */
extern "C" void kernel_launch(void* const* d_in, const int* in_sizes, int n_in,
                              void* d_out, int out_size)
{
    const float* x = nullptr;
    const float* Wqkv = nullptr;
    const float* Wproj = nullptr;
    const float* bproj = nullptr;
    for (int i = 0; i < n_in; i++) {
        switch (in_sizes[i]) {
            case 8388608: x     = (const float*)d_in[i]; break;
            case 3145728: Wqkv  = (const float*)d_in[i]; break;
            case 1048576: Wproj = (const float*)d_in[i]; break;
            case 1024:    bproj = (const float*)d_in[i]; break;
            default: break;
        }
    }
    float* out = (float*)d_out;

    /* QKV GEMM (inline convert, no pre-split) */
    {
        dim3 grid(3 * DIMV / 128, MTOT / 128);
        gemm_qkv<<<grid, 256>>>(x, Wqkv);
    }

    /* tensor-core attention -> o bf16 hi/lo planes */
    {
        size_t smem = (size_t)(2 * 128 + 4 * 64) * QP * sizeof(__nv_bfloat16);
        cudaFuncSetAttribute(attn_mma, cudaFuncAttributeMaxDynamicSharedMemorySize,
                             (int)smem);
        dim3 grid(SEQ / 128, BATCH * HEADS);
        attn_mma<<<grid, 256, smem>>>();
    }

    /* projection GEMM (A from planes, W inline) + bias */
    {
        dim3 grid(DIMV / 128, MTOT / 128);
        gemm_proj<<<grid, 256>>>(Wproj, bproj, out);
    }
    (void)out_size; (void)n_in;
}

// round 13
// speedup vs baseline: 1.7772x; 1.0047x over previous
#include <cuda_runtime.h>
#include <cuda_bf16.h>
#include <math.h>
#include <stdint.h>

#define DIMV   1024
#define HEADS  16
#define HD     64
#define BATCH  8
#define SEQ    1024
#define MTOT   (BATCH*SEQ)
#define SCALEF 0.125f

/* ------------------------------------------------------------------ */
/* scratch planes                                                      */
/* ------------------------------------------------------------------ */
#define PLANE (BATCH*HEADS*SEQ*HD)
__device__ __nv_bfloat16 g_qh[PLANE], g_ql[PLANE];
__device__ __nv_bfloat16 g_kh[PLANE], g_kl[PLANE];
__device__ __nv_bfloat16 g_vh[PLANE], g_vl[PLANE];
__device__ __nv_bfloat16 g_oh[(size_t)MTOT*DIMV], g_ol[(size_t)MTOT*DIMV];

__device__ __forceinline__ uint32_t smem_u32(const void* p) {
    uint32_t a;
    asm("{ .reg .u64 t; cvta.to.shared.u64 t, %1; cvt.u32.u64 %0, t; }"
        : "=r"(a) : "l"(p));
    return a;
}
__device__ __forceinline__ void ldm_x4(uint32_t* r, uint32_t addr) {
    asm volatile("ldmatrix.sync.aligned.m8n8.x4.shared.b16 {%0,%1,%2,%3}, [%4];"
                 : "=r"(r[0]), "=r"(r[1]), "=r"(r[2]), "=r"(r[3]) : "r"(addr));
}
__device__ __forceinline__ void ldm_x4_t(uint32_t* r, uint32_t addr) {
    asm volatile("ldmatrix.sync.aligned.m8n8.x4.trans.shared.b16 {%0,%1,%2,%3}, [%4];"
                 : "=r"(r[0]), "=r"(r[1]), "=r"(r[2]), "=r"(r[3]) : "r"(addr));
}
__device__ __forceinline__ void mma_bf16(float* c, const uint32_t* a, const uint32_t* b) {
    asm volatile("mma.sync.aligned.m16n8k16.row.col.f32.bf16.bf16.f32 "
                 "{%0,%1,%2,%3}, {%4,%5,%6,%7}, {%8,%9}, {%0,%1,%2,%3};"
                 : "+f"(c[0]), "+f"(c[1]), "+f"(c[2]), "+f"(c[3])
                 : "r"(a[0]), "r"(a[1]), "r"(a[2]), "r"(a[3]), "r"(b[0]), "r"(b[1]));
}

/* ------------------------------------------------------------------ */
/* GEMM BK=64: 128x128 tile, 8 warps 2x4, 2 CTA/SM, dynamic smem.      */
/* SPK=72 row (144 B): 16B-aligned, conflict-free ldmatrix phases.     */
/* ------------------------------------------------------------------ */
#define SPK   72
#define PL_E  (128*SPK)          /* elems per plane: 9216 */
#define GS_B  (4*PL_E*2)         /* 73728 bytes */

/* QKV: fp32 x, W inline-split; epilogue -> q/k/v planes (Q scaled) */
__global__ void __launch_bounds__(256, 2) gemm_qkv(
    const float* __restrict__ Ap, const float* __restrict__ Bw)
{
    extern __shared__ __nv_bfloat16 smg[];
    const uint32_t s0 = smem_u32(smg);
    const uint32_t uAh = s0;
    const uint32_t uAl = s0 + PL_E * 2;
    const uint32_t uBh = s0 + 2 * PL_E * 2;
    const uint32_t uBl = s0 + 3 * PL_E * 2;

    const int tid  = threadIdx.x;
    const int lane = tid & 31;
    const int wid  = tid >> 5;
    const int wm   = wid >> 2;
    const int wn   = wid & 3;
    const int m0   = blockIdx.y * 128;
    const int n0   = blockIdx.x * 128;

    const int a_lrow = (lane & 7) + ((lane >> 3) & 1) * 8;
    const int a_lkof = (lane >> 4) * 8;
    const int b_lrow = (lane & 7) + (lane >> 4) * 8;
    const int b_lkof = ((lane >> 3) & 1) * 8;

    float acc[4][4][4];
#pragma unroll
    for (int i = 0; i < 4; i++)
#pragma unroll
        for (int j = 0; j < 4; j++)
#pragma unroll
            for (int r = 0; r < 4; r++) acc[i][j][r] = 0.f;

    for (int k0 = 0; k0 < DIMV; k0 += 64) {
        /* load+split 128x64 fp32 of A and B */
#pragma unroll
        for (int j = 0; j < 8; j++) {
            int v   = tid + j * 256;       /* 0..2047 */
            int row = v >> 4;              /* 0..127  */
            int q   = v & 15;              /* float4 col */
            uint32_t so = (uint32_t)(row * SPK + q * 4) * 2;

            float4 a = *(const float4*)&Ap[(size_t)(m0 + row) * DIMV + k0 + q * 4];
            __nv_bfloat162 h01 = __floats2bfloat162_rn(a.x, a.y);
            __nv_bfloat162 h23 = __floats2bfloat162_rn(a.z, a.w);
            __nv_bfloat162 l01 = __floats2bfloat162_rn(a.x - __bfloat162float(h01.x),
                                                       a.y - __bfloat162float(h01.y));
            __nv_bfloat162 l23 = __floats2bfloat162_rn(a.z - __bfloat162float(h23.x),
                                                       a.w - __bfloat162float(h23.y));
            asm volatile("st.shared.v2.u32 [%0], {%1,%2};" ::
                "r"(uAh + so), "r"(*(uint32_t*)&h01), "r"(*(uint32_t*)&h23));
            asm volatile("st.shared.v2.u32 [%0], {%1,%2};" ::
                "r"(uAl + so), "r"(*(uint32_t*)&l01), "r"(*(uint32_t*)&l23));

            float4 b = *(const float4*)&Bw[(size_t)(n0 + row) * DIMV + k0 + q * 4];
            __nv_bfloat162 bh01 = __floats2bfloat162_rn(b.x, b.y);
            __nv_bfloat162 bh23 = __floats2bfloat162_rn(b.z, b.w);
            __nv_bfloat162 bl01 = __floats2bfloat162_rn(b.x - __bfloat162float(bh01.x),
                                                        b.y - __bfloat162float(bh01.y));
            __nv_bfloat162 bl23 = __floats2bfloat162_rn(b.z - __bfloat162float(bh23.x),
                                                        b.w - __bfloat162float(bh23.y));
            asm volatile("st.shared.v2.u32 [%0], {%1,%2};" ::
                "r"(uBh + so), "r"(*(uint32_t*)&bh01), "r"(*(uint32_t*)&bh23));
            asm volatile("st.shared.v2.u32 [%0], {%1,%2};" ::
                "r"(uBl + so), "r"(*(uint32_t*)&bl01), "r"(*(uint32_t*)&bl23));
        }
        __syncthreads();

#pragma unroll
        for (int ks = 0; ks < 4; ks++) {
            const int kk = ks * 16;
            uint32_t bfh[2][4], bfl[2][4];
#pragma unroll
            for (int bi = 0; bi < 2; bi++) {
                uint32_t boff = (uint32_t)((wn * 32 + bi * 16 + b_lrow) * SPK
                                           + kk + b_lkof) * 2;
                ldm_x4(bfh[bi], uBh + boff);
                ldm_x4(bfl[bi], uBl + boff);
            }
#pragma unroll
            for (int mi = 0; mi < 4; mi++) {
                uint32_t af_h[4], af_l[4];
                uint32_t aoff = (uint32_t)((wm * 64 + mi * 16 + a_lrow) * SPK
                                           + kk + a_lkof) * 2;
                ldm_x4(af_h, uAh + aoff);
                ldm_x4(af_l, uAl + aoff);
#pragma unroll
                for (int ni = 0; ni < 4; ni++) {
                    const uint32_t* bh = &bfh[ni >> 1][(ni & 1) * 2];
                    const uint32_t* bl = &bfl[ni >> 1][(ni & 1) * 2];
                    mma_bf16(acc[mi][ni], af_h, bh);
                    mma_bf16(acc[mi][ni], af_h, bl);
                    mma_bf16(acc[mi][ni], af_l, bh);
                }
            }
        }
        __syncthreads();
    }

    const int r_base = wm * 64 + (lane >> 2);
    const int c_base = wn * 32 + (lane & 3) * 2;
#pragma unroll
    for (int mi = 0; mi < 4; mi++) {
#pragma unroll
        for (int ni = 0; ni < 4; ni++) {
            int gcol = n0 + c_base + ni * 8;
#pragma unroll
            for (int half = 0; half < 2; half++) {
                int grow = m0 + r_base + mi * 16 + half * 8;
                float v0 = acc[mi][ni][half * 2 + 0];
                float v1 = acc[mi][ni][half * 2 + 1];
                int qkv = gcol >> 10;
                int hh  = (gcol >> 6) & 15;
                int dd  = gcol & 63;
                int b   = grow >> 10;
                int sp  = grow & 1023;
                size_t off = (((size_t)(b * HEADS + hh) * SEQ) + sp) * HD + dd;
                if (qkv == 0) { v0 *= SCALEF; v1 *= SCALEF; }
                __nv_bfloat16 h0 = __float2bfloat16_rn(v0);
                __nv_bfloat16 h1 = __float2bfloat16_rn(v1);
                __nv_bfloat16 l0 = __float2bfloat16_rn(v0 - __bfloat162float(h0));
                __nv_bfloat16 l1 = __float2bfloat16_rn(v1 - __bfloat162float(h1));
                __nv_bfloat16* ph = (qkv == 0) ? g_qh : (qkv == 1) ? g_kh : g_vh;
                __nv_bfloat16* pl = (qkv == 0) ? g_ql : (qkv == 1) ? g_kl : g_vl;
                *(__nv_bfloat162*)&ph[off] = __halves2bfloat162(h0, h1);
                *(__nv_bfloat162*)&pl[off] = __halves2bfloat162(l0, l1);
            }
        }
    }
}

/* Proj: A from bf16 o-planes (direct), W fp32 inline-split, +bias */
__global__ void __launch_bounds__(256, 2) gemm_proj(
    const float* __restrict__ Bw, const float* __restrict__ bias,
    float* __restrict__ out)
{
    extern __shared__ __nv_bfloat16 smg[];
    const uint32_t s0 = smem_u32(smg);
    const uint32_t uAh = s0;
    const uint32_t uAl = s0 + PL_E * 2;
    const uint32_t uBh = s0 + 2 * PL_E * 2;
    const uint32_t uBl = s0 + 3 * PL_E * 2;

    const int tid  = threadIdx.x;
    const int lane = tid & 31;
    const int wid  = tid >> 5;
    const int wm   = wid >> 2;
    const int wn   = wid & 3;
    const int m0   = blockIdx.y * 128;
    const int n0   = blockIdx.x * 128;

    const int a_lrow = (lane & 7) + ((lane >> 3) & 1) * 8;
    const int a_lkof = (lane >> 4) * 8;
    const int b_lrow = (lane & 7) + (lane >> 4) * 8;
    const int b_lkof = ((lane >> 3) & 1) * 8;

    float acc[4][4][4];
#pragma unroll
    for (int i = 0; i < 4; i++)
#pragma unroll
        for (int j = 0; j < 4; j++)
#pragma unroll
            for (int r = 0; r < 4; r++) acc[i][j][r] = 0.f;

    for (int k0 = 0; k0 < DIMV; k0 += 64) {
        /* A: direct bf16 plane copies: 128x64 per plane = 1024 x16B */
#pragma unroll
        for (int j = 0; j < 4; j++) {
            int v   = tid + j * 256;       /* 0..1023 */
            int row = v >> 3;              /* 0..127  */
            int c8  = (v & 7) * 8;         /* bf16 col */
            uint32_t so = (uint32_t)(row * SPK + c8) * 2;
            size_t go = (size_t)(m0 + row) * DIMV + k0 + c8;
            uint4 ah = *(const uint4*)&g_oh[go];
            uint4 al = *(const uint4*)&g_ol[go];
            asm volatile("st.shared.v4.b32 [%0], {%1,%2,%3,%4};" ::
                "r"(uAh + so), "r"(ah.x), "r"(ah.y), "r"(ah.z), "r"(ah.w));
            asm volatile("st.shared.v4.b32 [%0], {%1,%2,%3,%4};" ::
                "r"(uAl + so), "r"(al.x), "r"(al.y), "r"(al.z), "r"(al.w));
        }
        /* B: fp32 load + split, 128x64 */
#pragma unroll
        for (int j = 0; j < 8; j++) {
            int v   = tid + j * 256;
            int row = v >> 4;
            int q   = v & 15;
            uint32_t so = (uint32_t)(row * SPK + q * 4) * 2;
            float4 b = *(const float4*)&Bw[(size_t)(n0 + row) * DIMV + k0 + q * 4];
            __nv_bfloat162 bh01 = __floats2bfloat162_rn(b.x, b.y);
            __nv_bfloat162 bh23 = __floats2bfloat162_rn(b.z, b.w);
            __nv_bfloat162 bl01 = __floats2bfloat162_rn(b.x - __bfloat162float(bh01.x),
                                                        b.y - __bfloat162float(bh01.y));
            __nv_bfloat162 bl23 = __floats2bfloat162_rn(b.z - __bfloat162float(bh23.x),
                                                        b.w - __bfloat162float(bh23.y));
            asm volatile("st.shared.v2.u32 [%0], {%1,%2};" ::
                "r"(uBh + so), "r"(*(uint32_t*)&bh01), "r"(*(uint32_t*)&bh23));
            asm volatile("st.shared.v2.u32 [%0], {%1,%2};" ::
                "r"(uBl + so), "r"(*(uint32_t*)&bl01), "r"(*(uint32_t*)&bl23));
        }
        __syncthreads();

#pragma unroll
        for (int ks = 0; ks < 4; ks++) {
            const int kk = ks * 16;
            uint32_t bfh[2][4], bfl[2][4];
#pragma unroll
            for (int bi = 0; bi < 2; bi++) {
                uint32_t boff = (uint32_t)((wn * 32 + bi * 16 + b_lrow) * SPK
                                           + kk + b_lkof) * 2;
                ldm_x4(bfh[bi], uBh + boff);
                ldm_x4(bfl[bi], uBl + boff);
            }
#pragma unroll
            for (int mi = 0; mi < 4; mi++) {
                uint32_t af_h[4], af_l[4];
                uint32_t aoff = (uint32_t)((wm * 64 + mi * 16 + a_lrow) * SPK
                                           + kk + a_lkof) * 2;
                ldm_x4(af_h, uAh + aoff);
                ldm_x4(af_l, uAl + aoff);
#pragma unroll
                for (int ni = 0; ni < 4; ni++) {
                    const uint32_t* bh = &bfh[ni >> 1][(ni & 1) * 2];
                    const uint32_t* bl = &bfl[ni >> 1][(ni & 1) * 2];
                    mma_bf16(acc[mi][ni], af_h, bh);
                    mma_bf16(acc[mi][ni], af_h, bl);
                    mma_bf16(acc[mi][ni], af_l, bh);
                }
            }
        }
        __syncthreads();
    }

    const int r_base = wm * 64 + (lane >> 2);
    const int c_base = wn * 32 + (lane & 3) * 2;
#pragma unroll
    for (int mi = 0; mi < 4; mi++) {
#pragma unroll
        for (int ni = 0; ni < 4; ni++) {
            int gcol = n0 + c_base + ni * 8;
#pragma unroll
            for (int half = 0; half < 2; half++) {
                int grow = m0 + r_base + mi * 16 + half * 8;
                float2 bb = *(const float2*)&bias[gcol];
                *(float2*)&out[(size_t)grow * DIMV + gcol] =
                    make_float2(acc[mi][ni][half * 2 + 0] + bb.x,
                                acc[mi][ni][half * 2 + 1] + bb.y);
            }
        }
    }
}

/* ------------------------------------------------------------------ */
/* Tensor-core flash attention (proven), epilogue -> o planes          */
/* ------------------------------------------------------------------ */
#define QP 72

__global__ void __launch_bounds__(256) attn_mma()
{
    extern __shared__ __nv_bfloat16 smb[];
    __nv_bfloat16* Qh = smb;
    __nv_bfloat16* Ql = Qh + 128 * QP;
    __nv_bfloat16* Kh = Ql + 128 * QP;
    __nv_bfloat16* Kl = Kh + 64 * QP;
    __nv_bfloat16* Vh = Kl + 64 * QP;
    __nv_bfloat16* Vl = Vh + 64 * QP;

    const uint32_t uQh = smem_u32(Qh), uQl = smem_u32(Ql);
    const uint32_t uKh = smem_u32(Kh), uKl = smem_u32(Kl);
    const uint32_t uVh = smem_u32(Vh), uVl = smem_u32(Vl);

    const int tid  = threadIdx.x;
    const int lane = tid & 31;
    const int wid  = tid >> 5;
    const int bh   = blockIdx.y;
    const int m0   = blockIdx.x * 128;

    const size_t pbase = (size_t)bh * SEQ * HD;
    const __nv_bfloat16* pqh = g_qh + pbase;
    const __nv_bfloat16* pql = g_ql + pbase;
    const __nv_bfloat16* pkh = g_kh + pbase;
    const __nv_bfloat16* pkl = g_kl + pbase;
    const __nv_bfloat16* pvh = g_vh + pbase;
    const __nv_bfloat16* pvl = g_vl + pbase;

#pragma unroll
    for (int t = 0; t < 8; t++) {
        int idx = t * 256 + tid;
        int row = idx >> 4;
        int g   = idx & 15;
        size_t go = (size_t)(m0 + row) * HD + g * 4;
        *(uint2*)&Qh[row * QP + g * 4] = *(const uint2*)&pqh[go];
        *(uint2*)&Ql[row * QP + g * 4] = *(const uint2*)&pql[go];
    }

    float o[8][4];
#pragma unroll
    for (int n = 0; n < 8; n++)
#pragma unroll
        for (int r = 0; r < 4; r++) o[n][r] = 0.f;
    float mrow[2] = {-1e30f, -1e30f};
    float lrow[2] = {0.f, 0.f};

    const int a_row = wid * 16 + (lane & 15);
    const int a_kof = (lane >> 4) * 8;
    const int b_row = (lane & 7) + (lane >> 4) * 8;
    const int b_kof = ((lane >> 3) & 1) * 8;
    const int v_key = ((lane >> 3) & 1) * 8 + (lane & 7);
    const int v_col = (lane >> 4) * 8;

    for (int c = 0; c < 16; c++) {
        const int key0 = c * 64;
        __syncthreads();
#pragma unroll
        for (int t = 0; t < 4; t++) {
            int idx = t * 256 + tid;
            int row = idx >> 4;
            int g   = idx & 15;
            size_t go = (size_t)(key0 + row) * HD + g * 4;
            uint32_t so = row * QP + g * 4;
            *(uint2*)&Kh[so] = *(const uint2*)&pkh[go];
            *(uint2*)&Kl[so] = *(const uint2*)&pkl[go];
            *(uint2*)&Vh[so] = *(const uint2*)&pvh[go];
            *(uint2*)&Vl[so] = *(const uint2*)&pvl[go];
        }
        __syncthreads();

        float s[8][4];
#pragma unroll
        for (int n = 0; n < 8; n++)
#pragma unroll
            for (int r = 0; r < 4; r++) s[n][r] = 0.f;

#pragma unroll
        for (int kk = 0; kk < 4; kk++) {
            uint32_t qhf[4], qlf[4];
            uint32_t aoff = (uint32_t)(a_row * QP + kk * 16 + a_kof) * 2;
            ldm_x4(qhf, uQh + aoff);
            ldm_x4(qlf, uQl + aoff);

            uint32_t kbh[4][4], kbl[4][4];
#pragma unroll
            for (int bi = 0; bi < 4; bi++) {
                uint32_t boff = (uint32_t)((bi * 16 + b_row) * QP + kk * 16 + b_kof) * 2;
                ldm_x4(kbh[bi], uKh + boff);
                ldm_x4(kbl[bi], uKl + boff);
            }
#pragma unroll
            for (int ni = 0; ni < 8; ni++)
                mma_bf16(s[ni], qhf, &kbh[ni >> 1][(ni & 1) * 2]);
#pragma unroll
            for (int ni = 0; ni < 8; ni++)
                mma_bf16(s[ni], qhf, &kbl[ni >> 1][(ni & 1) * 2]);
#pragma unroll
            for (int ni = 0; ni < 8; ni++)
                mma_bf16(s[ni], qlf, &kbh[ni >> 1][(ni & 1) * 2]);
        }

        float alpha[2];
#pragma unroll
        for (int r = 0; r < 2; r++) {
            float mx = -1e30f;
#pragma unroll
            for (int ni = 0; ni < 8; ni++)
                mx = fmaxf(mx, fmaxf(s[ni][r * 2], s[ni][r * 2 + 1]));
            mx = fmaxf(mx, __shfl_xor_sync(0xffffffffu, mx, 1));
            mx = fmaxf(mx, __shfl_xor_sync(0xffffffffu, mx, 2));
            float mnew = fmaxf(mrow[r], mx);
            alpha[r] = __expf(mrow[r] - mnew);
            mrow[r] = mnew;
            float ls = 0.f;
#pragma unroll
            for (int ni = 0; ni < 8; ni++) {
                s[ni][r * 2]     = __expf(s[ni][r * 2]     - mnew);
                s[ni][r * 2 + 1] = __expf(s[ni][r * 2 + 1] - mnew);
                ls += s[ni][r * 2] + s[ni][r * 2 + 1];
            }
            ls += __shfl_xor_sync(0xffffffffu, ls, 1);
            ls += __shfl_xor_sync(0xffffffffu, ls, 2);
            lrow[r] = lrow[r] * alpha[r] + ls;
#pragma unroll
            for (int ni = 0; ni < 8; ni++) {
                o[ni][r * 2]     *= alpha[r];
                o[ni][r * 2 + 1] *= alpha[r];
            }
        }

#pragma unroll
        for (int kk = 0; kk < 4; kk++) {
            uint32_t pha[4], pla[4];
#pragma unroll
            for (int q = 0; q < 4; q++) {
                float f0 = (q & 2) ? s[2 * kk + 1][(q & 1) * 2]     : s[2 * kk][(q & 1) * 2];
                float f1 = (q & 2) ? s[2 * kk + 1][(q & 1) * 2 + 1] : s[2 * kk][(q & 1) * 2 + 1];
                __nv_bfloat162 h2 = __floats2bfloat162_rn(f0, f1);
                __nv_bfloat162 l2 = __floats2bfloat162_rn(f0 - __bfloat162float(h2.x),
                                                          f1 - __bfloat162float(h2.y));
                pha[q] = *(uint32_t*)&h2;
                pla[q] = *(uint32_t*)&l2;
            }
            uint32_t vbh[4][4], vbl[4][4];
#pragma unroll
            for (int np = 0; np < 4; np++) {
                uint32_t voff = (uint32_t)((kk * 16 + v_key) * QP + np * 16 + v_col) * 2;
                ldm_x4_t(vbh[np], uVh + voff);
                ldm_x4_t(vbl[np], uVl + voff);
            }
#pragma unroll
            for (int ni = 0; ni < 8; ni++)
                mma_bf16(o[ni], pha, &vbh[ni >> 1][(ni & 1) * 2]);
#pragma unroll
            for (int ni = 0; ni < 8; ni++)
                mma_bf16(o[ni], pha, &vbl[ni >> 1][(ni & 1) * 2]);
#pragma unroll
            for (int ni = 0; ni < 8; ni++)
                mma_bf16(o[ni], pla, &vbh[ni >> 1][(ni & 1) * 2]);
        }
    }

    const int b = bh >> 4;
    const int h = bh & 15;
#pragma unroll
    for (int r = 0; r < 2; r++) {
        float inv = 1.f / lrow[r];
        int row = m0 + wid * 16 + (lane >> 2) + r * 8;
        size_t base = ((size_t)(b * SEQ + row)) * DIMV + h * HD + (lane & 3) * 2;
#pragma unroll
        for (int ni = 0; ni < 8; ni++) {
            float f0 = o[ni][r * 2] * inv;
            float f1 = o[ni][r * 2 + 1] * inv;
            __nv_bfloat162 h2 = __floats2bfloat162_rn(f0, f1);
            __nv_bfloat162 l2 = __floats2bfloat162_rn(f0 - __bfloat162float(h2.x),
                                                      f1 - __bfloat162float(h2.y));
            *(__nv_bfloat162*)&g_oh[base + ni * 8] = h2;
            *(__nv_bfloat162*)&g_ol[base + ni * 8] = l2;
        }
    }
}

/* ------------------------------------------------------------------ */
extern "C" void kernel_launch(void* const* d_in, const int* in_sizes, int n_in,
                              void* d_out, int out_size)
{
    const float* x = nullptr;
    const float* Wqkv = nullptr;
    const float* Wproj = nullptr;
    const float* bproj = nullptr;
    for (int i = 0; i < n_in; i++) {
        switch (in_sizes[i]) {
            case 8388608: x     = (const float*)d_in[i]; break;
            case 3145728: Wqkv  = (const float*)d_in[i]; break;
            case 1048576: Wproj = (const float*)d_in[i]; break;
            case 1024:    bproj = (const float*)d_in[i]; break;
            default: break;
        }
    }
    float* out = (float*)d_out;

    /* QKV GEMM (BK=64, 2 CTA/SM) */
    {
        cudaFuncSetAttribute(gemm_qkv, cudaFuncAttributeMaxDynamicSharedMemorySize,
                             GS_B);
        dim3 grid(3 * DIMV / 128, MTOT / 128);
        gemm_qkv<<<grid, 256, GS_B>>>(x, Wqkv);
    }

    /* tensor-core attention -> o bf16 hi/lo planes */
    {
        size_t smem = (size_t)(2 * 128 + 4 * 64) * QP * sizeof(__nv_bfloat16);
        cudaFuncSetAttribute(attn_mma, cudaFuncAttributeMaxDynamicSharedMemorySize,
                             (int)smem);
        dim3 grid(SEQ / 128, BATCH * HEADS);
        attn_mma<<<grid, 256, smem>>>();
    }

    /* projection GEMM (BK=64) + bias */
    {
        cudaFuncSetAttribute(gemm_proj, cudaFuncAttributeMaxDynamicSharedMemorySize,
                             GS_B);
        dim3 grid(DIMV / 128, MTOT / 128);
        gemm_proj<<<grid, 256, GS_B>>>(Wproj, bproj, out);
    }
    (void)out_size; (void)n_in;
}